// round 4
// baseline (speedup 1.0000x reference)
#include <cuda_runtime.h>

// Problem constants
//   z:        [32, 512, 32, 32] f32  (B, C, H, W)
//   codebook: [1024, 512] f32        (K, D)
// Outputs (concatenated, f32):
//   quantized: 16,777,216 elements, then indices: 32,768 elements (as float)

#define N_ROWS   32768
#define K_CODES  1024
#define DIM      512
#define HW       1024
#define QUANT_ELEMS 16777216

__device__ float g_codenorm[K_CODES];
__device__ int   g_index[N_ROWS];

// packed fp32x2 FMA (per-lane IEEE fma, same rounding as scalar FFMA chain)
__device__ __forceinline__ void ffma2(float2& d, float2 a, float2 b) {
    asm("fma.rn.f32x2 %0, %1, %2, %0;"
        : "+l"(reinterpret_cast<unsigned long long&>(d))
        : "l"(reinterpret_cast<unsigned long long&>(a)),
          "l"(reinterpret_cast<unsigned long long&>(b)));
}

// ---------------------------------------------------------------------------
// Kernel 0: per-code norms, replicating XLA CPU (NEON-4) vectorized reduce:
//   t_j = sum_i fl(w[4i+j]^2)   (rounded square, rounded sequential adds)
//   C   = fl( fl(t0+t2) + fl(t1+t3) )
// Block: 256 threads = 64 codes x 4 lanes.
// ---------------------------------------------------------------------------
__global__ void codenorm_kernel(const float* __restrict__ cb) {
    __shared__ float part[4][64];
    const int t = threadIdx.x;
    const int j = t >> 6;          // strided lane 0..3
    const int cc = t & 63;         // code within block
    const int code = blockIdx.x * 64 + cc;
    const float* row = cb + (size_t)code * DIM;
    float acc = 0.f;
#pragma unroll 8
    for (int i = 0; i < DIM / 4; ++i) {
        float v = __ldg(row + 4 * i + j);
        acc = __fadd_rn(acc, __fmul_rn(v, v));
    }
    part[j][cc] = acc;
    __syncthreads();
    if (t < 64) {
        float u0 = __fadd_rn(part[0][t], part[2][t]);
        float u1 = __fadd_rn(part[1][t], part[3][t]);
        g_codenorm[blockIdx.x * 64 + t] = __fadd_rn(u0, u1);
    }
}

// ---------------------------------------------------------------------------
// Kernel 1: fused distance GEMM + argmin
// 128 rows x 128 codes x 16 K per iter, 256 threads, 8x8/thread, FFMA2.
// Per (n,k): SINGLE accumulator, ascending-c fma chain (Eigen gebp order).
// ---------------------------------------------------------------------------
__global__ void __launch_bounds__(256, 2)
vq_argmin_kernel(const float* __restrict__ z, const float* __restrict__ cb,
                 float* __restrict__ out)
{
    __shared__ float zs[16][128];     // [k][row]
    __shared__ float ws[16][128];     // [k][code]
    __shared__ float As[128];         // per-row ||z||^2 (XLA order)
    __shared__ float part4[4][128];   // strided-lane partials for A
    __shared__ float redv[128][16];
    __shared__ int   redi[128][16];

    const int t  = threadIdx.x;
    const int tx = t & 15;
    const int ty = t >> 4;
    const int b   = blockIdx.x >> 3;
    const int hw0 = (blockIdx.x & 7) << 7;

    const float* zb = z + (size_t)b * DIM * HW + hw0;

    // ---- prologue: A[r] replicating NEON-4 strided reduce + ShuffleAndAdd ----
#pragma unroll
    for (int s = 0; s < 2; ++s) {
        const int rj = t + 256 * s;
        const int r  = rj & 127;
        const int j  = rj >> 7;       // lane 0..3 across the two passes
        float acc = 0.f;
#pragma unroll 8
        for (int i = 0; i < DIM / 4; ++i) {
            float v = __ldg(zb + (size_t)(4 * i + j) * HW + r);
            acc = __fadd_rn(acc, __fmul_rn(v, v));
        }
        part4[j][r] = acc;
    }
    __syncthreads();
    if (t < 128) {
        float u0 = __fadd_rn(part4[0][t], part4[2][t]);
        float u1 = __fadd_rn(part4[1][t], part4[3][t]);
        As[t] = __fadd_rn(u0, u1);
    }
    __syncthreads();

    float bestv[8];
    int   besti[8];
#pragma unroll
    for (int i = 0; i < 8; ++i) { bestv[i] = 3.402823466e38f; besti[i] = 0; }

    for (int nt = 0; nt < 8; ++nt) {
        const int n0 = nt << 7;

        float2 acc[8][4];
#pragma unroll
        for (int i = 0; i < 8; ++i)
#pragma unroll
            for (int j = 0; j < 4; ++j) acc[i][j] = make_float2(0.f, 0.f);

        for (int kt = 0; kt < 32; ++kt) {            // ascending c tiles
            const int c0 = kt << 4;
            __syncthreads();
            {   // z tile: 16 c-planes x 128 rows (coalesced along hw)
                const int ck = t >> 4, ln = t & 15;
                const float4* s4 =
                    reinterpret_cast<const float4*>(zb + (size_t)(c0 + ck) * HW + ln * 8);
                float4 v0 = __ldg(s4), v1 = __ldg(s4 + 1);
                *reinterpret_cast<float4*>(&zs[ck][ln * 8])     = v0;
                *reinterpret_cast<float4*>(&zs[ck][ln * 8 + 4]) = v1;
            }
            {   // codebook tile: 128 codes x 16 c (transposed into smem)
                const int r = t >> 1, hf = t & 1;
                const float4* s4 =
                    reinterpret_cast<const float4*>(cb + (size_t)(n0 + r) * DIM + c0 + hf * 8);
                float4 v0 = __ldg(s4), v1 = __ldg(s4 + 1);
                const int cc = hf * 8;
                ws[cc + 0][r] = v0.x; ws[cc + 1][r] = v0.y;
                ws[cc + 2][r] = v0.z; ws[cc + 3][r] = v0.w;
                ws[cc + 4][r] = v1.x; ws[cc + 5][r] = v1.y;
                ws[cc + 6][r] = v1.z; ws[cc + 7][r] = v1.w;
            }
            __syncthreads();

#pragma unroll
            for (int kk = 0; kk < 16; ++kk) {        // ascending c within tile
                float a[8];
                *reinterpret_cast<float4*>(a) =
                    *reinterpret_cast<const float4*>(&zs[kk][ty * 8]);
                *reinterpret_cast<float4*>(a + 4) =
                    *reinterpret_cast<const float4*>(&zs[kk][ty * 8 + 4]);
                float2 bb[4];
                *reinterpret_cast<float4*>(&bb[0]) =
                    *reinterpret_cast<const float4*>(&ws[kk][tx * 8]);
                *reinterpret_cast<float4*>(&bb[2]) =
                    *reinterpret_cast<const float4*>(&ws[kk][tx * 8 + 4]);
#pragma unroll
                for (int i = 0; i < 8; ++i) {
                    float2 a2 = make_float2(a[i], a[i]);
#pragma unroll
                    for (int j = 0; j < 4; ++j) ffma2(acc[i][j], a2, bb[j]);
                }
            }
        }

        // epilogue: d = fl( fl(A - 2*M) + C ), explicit rounds; ascending code
        // order + strict < keeps the lowest index (jnp.argmin tie-break)
        float cn[8];
#pragma unroll
        for (int j = 0; j < 8; ++j) cn[j] = g_codenorm[n0 + tx * 8 + j];
#pragma unroll
        for (int i = 0; i < 8; ++i) {
            float Ar = As[ty * 8 + i];
#pragma unroll
            for (int j = 0; j < 4; ++j) {
                float t2a = __fadd_rn(Ar, __fmul_rn(-2.0f, acc[i][j].x));
                float t2b = __fadd_rn(Ar, __fmul_rn(-2.0f, acc[i][j].y));
                float d0 = __fadd_rn(t2a, cn[2 * j]);
                float d1 = __fadd_rn(t2b, cn[2 * j + 1]);
                int   i0 = n0 + tx * 8 + 2 * j;
                if (d0 < bestv[i]) { bestv[i] = d0; besti[i] = i0; }
                if (d1 < bestv[i]) { bestv[i] = d1; besti[i] = i0 + 1; }
            }
        }
    }

    // cross-thread argmin reduction per row
#pragma unroll
    for (int i = 0; i < 8; ++i) {
        redv[ty * 8 + i][tx] = bestv[i];
        redi[ty * 8 + i][tx] = besti[i];
    }
    __syncthreads();
    if (t < 128) {
        float bv = redv[t][0];
        int   bi = redi[t][0];
#pragma unroll
        for (int x = 1; x < 16; ++x) {
            float v  = redv[t][x];
            int   ix = redi[t][x];
            if (v < bv || (v == bv && ix < bi)) { bv = v; bi = ix; }
        }
        int n = b * HW + hw0 + t;
        g_index[n] = bi;
        out[QUANT_ELEMS + n] = (float)bi;
    }
}

// ---------------------------------------------------------------------------
// Kernel 2: gather quantized = codebook[idx] (float4 granularity, L2-resident cb)
// ---------------------------------------------------------------------------
__global__ void gather_kernel(const float* __restrict__ cb, float* __restrict__ out) {
    int i  = blockIdx.x * blockDim.x + threadIdx.x;
    int n  = i >> 7;
    int dd = i & 127;
    int idx = g_index[n];
    float4 v = __ldg(reinterpret_cast<const float4*>(cb) + (size_t)idx * 128 + dd);
    reinterpret_cast<float4*>(out)[i] = v;
}

// ---------------------------------------------------------------------------
extern "C" void kernel_launch(void* const* d_in, const int* in_sizes, int n_in,
                              void* d_out, int out_size) {
    const float* z  = (const float*)d_in[0];
    const float* cb = (const float*)d_in[1];
    float* out = (float*)d_out;

    codenorm_kernel<<<K_CODES / 64, 256>>>(cb);
    vq_argmin_kernel<<<256, 256>>>(z, cb, out);
    gather_kernel<<<QUANT_ELEMS / 4 / 256, 256>>>(cb, out);
}

// round 5
// speedup vs baseline: 1.0748x; 1.0748x over previous
#include <cuda_runtime.h>
#include <cstdint>

// Problem:
//   z:        [32, 512, 32, 32] f32  (B, C, H, W)
//   codebook: [1024, 512] f32        (K, D)
// Outputs (concatenated f32): quantized [16,777,216], then indices [32,768] as float.

#define N_ROWS   32768
#define K_CODES  1024
#define DIM      512
#define HW       1024
#define QUANT_ELEMS 16777216

#define CHUNK    32              // c per pipeline stage
#define NCHUNK   (DIM / CHUNK)   // 16

__device__ float g_codenorm[K_CODES];
__device__ int   g_index[N_ROWS];

// packed fp32x2 FMA (per-lane IEEE fma -> identical rounding to scalar chain)
__device__ __forceinline__ void ffma2(float2& d, float2 a, float2 b) {
    asm("fma.rn.f32x2 %0, %1, %2, %0;"
        : "+l"(reinterpret_cast<unsigned long long&>(d))
        : "l"(reinterpret_cast<unsigned long long&>(a)),
          "l"(reinterpret_cast<unsigned long long&>(b)));
}

__device__ __forceinline__ void cp_async16(uint32_t saddr, const void* g) {
    asm volatile("cp.async.ca.shared.global [%0], [%1], 16;\n"
                 :: "r"(saddr), "l"(g));
}
#define CP_COMMIT()  asm volatile("cp.async.commit_group;\n" ::: "memory")
#define CP_WAIT0()   asm volatile("cp.async.wait_group 0;\n" ::: "memory")

// ---------------------------------------------------------------------------
// Kernel 0: per-code norms, XLA CPU NEON-4 order:
//   t_j = sum_i fl(w[4i+j]^2);  C = fl( fl(t0+t2) + fl(t1+t3) )
// 128 threads = 32 codes x 4 lanes; shfl combine.
// ---------------------------------------------------------------------------
__global__ void codenorm_kernel(const float* __restrict__ cb) {
    const int t = threadIdx.x;
    const int j = t & 3;
    const int code = blockIdx.x * 32 + (t >> 2);
    const float* row = cb + (size_t)code * DIM;
    float acc = 0.f;
#pragma unroll 8
    for (int i = 0; i < DIM / 4; ++i) {
        float v = __ldg(row + 4 * i + j);
        acc = __fadd_rn(acc, __fmul_rn(v, v));
    }
    float u = __fadd_rn(acc, __shfl_down_sync(0xffffffffu, acc, 2)); // j0:t0+t2, j1:t1+t3
    float c = __fadd_rn(u,   __shfl_down_sync(0xffffffffu, u, 1));   // j0:(t0+t2)+(t1+t3)
    if (j == 0) g_codenorm[code] = c;
}

// ---------------------------------------------------------------------------
// Kernel 1: fused distance GEMM + argmin, double-buffered cp.async pipeline
// Block tile 128 rows x 128 codes; 256 threads, 8x8/thread, FFMA2.
// Dynamic smem layout (floats):
//   [0      .. 8192)  zs : 2 x 32 x 128   (z tile, [buf][c][row])
//   [8192   ..16384)  ws : 2 x 32 x 128   ([buf][c][code], transposed)
//   [16384  ..16512)  As : 128            (per-row ||z||^2, XLA order)
//   [16512  ..18560)  redv: 128 x 16      (running best value; aliases part4)
//   [18560  ..20608)  redi: 128 x 16      (running best index, int)
// ---------------------------------------------------------------------------
__global__ void __launch_bounds__(256, 2)
vq_argmin_kernel(const float* __restrict__ z, const float* __restrict__ cb,
                 float* __restrict__ out)
{
    extern __shared__ float sm[];
    float* zs   = sm;                 // [2][32][128]
    float* ws   = sm + 8192;          // [2][32][128]
    float* As   = sm + 16384;         // [128]
    float* redv = sm + 16512;         // [128][16]
    int*   redi = (int*)(sm + 18560); // [128][16]
    float* part4 = redv;              // prologue scratch [4][128], aliased

    const int t  = threadIdx.x;
    const int tx = t & 15;
    const int ty = t >> 4;
    const int b   = blockIdx.x >> 3;
    const int hw0 = (blockIdx.x & 7) << 7;

    const float* zb = z + (size_t)b * DIM * HW + hw0;

    const uint32_t zs_base = (uint32_t)__cvta_generic_to_shared(zs);

    // ---- prologue: A[r] via NEON-4 strided reduce + ShuffleAndAdd order ----
#pragma unroll
    for (int s = 0; s < 2; ++s) {
        const int rj = t + 256 * s;
        const int r  = rj & 127;
        const int j  = rj >> 7;
        float acc = 0.f;
#pragma unroll 8
        for (int i = 0; i < DIM / 4; ++i) {
            float v = __ldg(zb + (size_t)(4 * i + j) * HW + r);
            acc = __fadd_rn(acc, __fmul_rn(v, v));
        }
        part4[j * 128 + r] = acc;
    }
    __syncthreads();
    if (t < 128) {
        float u0 = __fadd_rn(part4[0 * 128 + t], part4[2 * 128 + t]);
        float u1 = __fadd_rn(part4[1 * 128 + t], part4[3 * 128 + t]);
        As[t] = __fadd_rn(u0, u1);
    }
    __syncthreads();

    // init running argmin slots (each (row, tx) owned by exactly one thread)
#pragma unroll
    for (int i = 0; i < 8; ++i) {
        redv[(ty * 8 + i) * 16 + tx] = 3.402823466e38f;
        redi[(ty * 8 + i) * 16 + tx] = 0;
    }

    // per-thread load descriptors
    const int zq_c[4] = { (t + 0) >> 5, (t + 256) >> 5, (t + 512) >> 5, (t + 768) >> 5 };
    const int zq_g = t & 31;                         // 16B group within 128-float row
    const int wn  = t >> 1;                          // code row 0..127
    const int wco = (t & 1) * 16;                    // c offset within chunk (0 or 16)

    for (int nt = 0; nt < 8; ++nt) {
        const int n0 = nt << 7;

        float2 acc[8][4];
#pragma unroll
        for (int i = 0; i < 8; ++i)
#pragma unroll
            for (int j = 0; j < 4; ++j) acc[i][j] = make_float2(0.f, 0.f);

        // ---- prefetch chunk 0 ----
        float4 W[4];
        {
            const float* wsrc = cb + (size_t)(n0 + wn) * DIM + wco;
#pragma unroll
            for (int m = 0; m < 4; ++m) W[m] = __ldg((const float4*)wsrc + m);
#pragma unroll
            for (int q = 0; q < 4; ++q)
                cp_async16(zs_base + (uint32_t)((zq_c[q] * 128 + zq_g * 4) * 4),
                           zb + (size_t)zq_c[q] * HW + zq_g * 4);
            CP_COMMIT();
        }

        for (int kt = 0; kt < NCHUNK; ++kt) {
            const int p = kt & 1;
            float* wp = ws + p * 4096;
            const float* zp = zs + p * 4096;

            __syncthreads();   // all warps done computing chunk kt-1 (frees ws[p] from kt-2)

            // store W(kt) into ws[p] (transpose)
#pragma unroll
            for (int m = 0; m < 4; ++m) {
                const int cc = wco + m * 4;
                wp[(cc + 0) * 128 + wn] = W[m].x;
                wp[(cc + 1) * 128 + wn] = W[m].y;
                wp[(cc + 2) * 128 + wn] = W[m].z;
                wp[(cc + 3) * 128 + wn] = W[m].w;
            }
            // prefetch W(kt+1) into regs
            if (kt + 1 < NCHUNK) {
                const float* wsrc = cb + (size_t)(n0 + wn) * DIM + (kt + 1) * CHUNK + wco;
#pragma unroll
                for (int m = 0; m < 4; ++m) W[m] = __ldg((const float4*)wsrc + m);
            }

            CP_WAIT0();        // z(kt) landed
            __syncthreads();   // ws[p] stores + zs[p] visible to all

            // prefetch z(kt+1) into the other buffer
            if (kt + 1 < NCHUNK) {
                const int c1 = (kt + 1) * CHUNK;
                const uint32_t dst = zs_base + (uint32_t)((p ^ 1) * 4096 * 4);
#pragma unroll
                for (int q = 0; q < 4; ++q)
                    cp_async16(dst + (uint32_t)((zq_c[q] * 128 + zq_g * 4) * 4),
                               zb + (size_t)(c1 + zq_c[q]) * HW + zq_g * 4);
                CP_COMMIT();
            }

            // ---- compute: 32 ascending-c steps (chain order == reference) ----
#pragma unroll
            for (int kk = 0; kk < CHUNK; ++kk) {
                float a[8];
                *reinterpret_cast<float4*>(a) =
                    *reinterpret_cast<const float4*>(zp + kk * 128 + ty * 8);
                *reinterpret_cast<float4*>(a + 4) =
                    *reinterpret_cast<const float4*>(zp + kk * 128 + ty * 8 + 4);
                float2 bb[4];
                *reinterpret_cast<float4*>(&bb[0]) =
                    *reinterpret_cast<const float4*>(wp + kk * 128 + tx * 8);
                *reinterpret_cast<float4*>(&bb[2]) =
                    *reinterpret_cast<const float4*>(wp + kk * 128 + tx * 8 + 4);
#pragma unroll
                for (int i = 0; i < 8; ++i) {
                    float2 a2 = make_float2(a[i], a[i]);
#pragma unroll
                    for (int j = 0; j < 4; ++j) ffma2(acc[i][j], a2, bb[j]);
                }
            }
        }

        // epilogue: d = fl( fl(A - 2M) + C ); strict < keeps lowest index
#pragma unroll
        for (int i = 0; i < 8; ++i) {
            const int row = ty * 8 + i;
            float Ar = As[row];
            float bv = redv[row * 16 + tx];
            int   bi = redi[row * 16 + tx];
#pragma unroll
            for (int j = 0; j < 4; ++j) {
                float cn0 = g_codenorm[n0 + tx * 8 + 2 * j];
                float cn1 = g_codenorm[n0 + tx * 8 + 2 * j + 1];
                float d0 = __fadd_rn(__fadd_rn(Ar, __fmul_rn(-2.0f, acc[i][j].x)), cn0);
                float d1 = __fadd_rn(__fadd_rn(Ar, __fmul_rn(-2.0f, acc[i][j].y)), cn1);
                int   i0 = n0 + tx * 8 + 2 * j;
                if (d0 < bv) { bv = d0; bi = i0; }
                if (d1 < bv) { bv = d1; bi = i0 + 1; }
            }
            redv[row * 16 + tx] = bv;
            redi[row * 16 + tx] = bi;
        }
    }

    // final cross-tx reduction per row
    __syncthreads();
    if (t < 128) {
        float bv = redv[t * 16];
        int   bi = redi[t * 16];
#pragma unroll
        for (int x = 1; x < 16; ++x) {
            float v  = redv[t * 16 + x];
            int   ix = redi[t * 16 + x];
            if (v < bv || (v == bv && ix < bi)) { bv = v; bi = ix; }
        }
        int n = b * HW + hw0 + t;
        g_index[n] = bi;
        out[QUANT_ELEMS + n] = (float)bi;
    }
}

// ---------------------------------------------------------------------------
// Kernel 2: gather quantized = codebook[idx] (float4, codebook L2-resident)
// ---------------------------------------------------------------------------
__global__ void gather_kernel(const float* __restrict__ cb, float* __restrict__ out) {
    int i  = blockIdx.x * blockDim.x + threadIdx.x;
    int n  = i >> 7;
    int dd = i & 127;
    int idx = g_index[n];
    float4 v = __ldg(reinterpret_cast<const float4*>(cb) + (size_t)idx * 128 + dd);
    reinterpret_cast<float4*>(out)[i] = v;
}

// ---------------------------------------------------------------------------
extern "C" void kernel_launch(void* const* d_in, const int* in_sizes, int n_in,
                              void* d_out, int out_size) {
    const float* z  = (const float*)d_in[0];
    const float* cb = (const float*)d_in[1];
    float* out = (float*)d_out;

    const int smem_bytes = 20608 * 4;  // 82,432 B
    cudaFuncSetAttribute(vq_argmin_kernel,
                         cudaFuncAttributeMaxDynamicSharedMemorySize, smem_bytes);

    codenorm_kernel<<<K_CODES / 32, 128>>>(cb);
    vq_argmin_kernel<<<256, 256, smem_bytes>>>(z, cb, out);
    gather_kernel<<<QUANT_ELEMS / 4 / 256, 256>>>(cb, out);
}

// round 6
// speedup vs baseline: 1.0759x; 1.0010x over previous
#include <cuda_runtime.h>
#include <cstdint>

// Problem:
//   z:        [32, 512, 32, 32] f32  (B, C, H, W)
//   codebook: [1024, 512] f32        (K, D)
// Outputs (concatenated f32): quantized [16,777,216], then indices [32,768] as float.

#define N_ROWS   32768
#define K_CODES  1024
#define DIM      512
#define HW       1024
#define QUANT_ELEMS 16777216

#define CHUNK    32              // c per pipeline stage
#define NCHUNK   (DIM / CHUNK)   // 16

__device__ float g_codenorm[K_CODES];
__device__ int   g_index[N_ROWS];

// packed fp32x2 FMA (per-lane IEEE fma -> identical rounding to scalar chain)
__device__ __forceinline__ void ffma2(float2& d, float2 a, float2 b) {
    asm("fma.rn.f32x2 %0, %1, %2, %0;"
        : "+l"(reinterpret_cast<unsigned long long&>(d))
        : "l"(reinterpret_cast<unsigned long long&>(a)),
          "l"(reinterpret_cast<unsigned long long&>(b)));
}

__device__ __forceinline__ void cp_async16(uint32_t saddr, const void* g) {
    asm volatile("cp.async.ca.shared.global [%0], [%1], 16;\n"
                 :: "r"(saddr), "l"(g));
}
#define CP_COMMIT()  asm volatile("cp.async.commit_group;\n" ::: "memory")
#define CP_WAIT0()   asm volatile("cp.async.wait_group 0;\n" ::: "memory")

// ---------------------------------------------------------------------------
// Kernel 0: per-code norms, XLA CPU NEON-4 order:
//   t_j = sum_i fl(w[4i+j]^2);  C = fl( fl(t0+t2) + fl(t1+t3) )
// 128 threads = 32 codes x 4 lanes; shfl combine.
// ---------------------------------------------------------------------------
__global__ void codenorm_kernel(const float* __restrict__ cb) {
    const int t = threadIdx.x;
    const int j = t & 3;
    const int code = blockIdx.x * 32 + (t >> 2);
    const float* row = cb + (size_t)code * DIM;
    float acc = 0.f;
#pragma unroll 8
    for (int i = 0; i < DIM / 4; ++i) {
        float v = __ldg(row + 4 * i + j);
        acc = __fadd_rn(acc, __fmul_rn(v, v));
    }
    float u = __fadd_rn(acc, __shfl_down_sync(0xffffffffu, acc, 2)); // j0:t0+t2, j1:t1+t3
    float c = __fadd_rn(u,   __shfl_down_sync(0xffffffffu, u, 1));   // j0:(t0+t2)+(t1+t3)
    if (j == 0) g_codenorm[code] = c;
}

// ---------------------------------------------------------------------------
// Kernel 1: fused distance GEMM + argmin, double-buffered cp.async pipeline
// Block tile 128 rows x 128 codes; 256 threads, 8x8/thread, FFMA2.
// Dynamic smem layout (floats):
//   [0      .. 8192)  zs : 2 x 32 x 128   (z tile, [buf][c][row])
//   [8192   ..16384)  ws : 2 x 32 x 128   ([buf][c][code], transposed)
//   [16384  ..16512)  As : 128            (per-row ||z||^2, XLA order)
//   [16512  ..18560)  redv: 128 x 16      (running best value; aliases part4)
//   [18560  ..20608)  redi: 128 x 16      (running best index, int)
// ---------------------------------------------------------------------------
__global__ void __launch_bounds__(256, 2)
vq_argmin_kernel(const float* __restrict__ z, const float* __restrict__ cb,
                 float* __restrict__ out)
{
    extern __shared__ float sm[];
    float* zs   = sm;                 // [2][32][128]
    float* ws   = sm + 8192;          // [2][32][128]
    float* As   = sm + 16384;         // [128]
    float* redv = sm + 16512;         // [128][16]
    int*   redi = (int*)(sm + 18560); // [128][16]
    float* part4 = redv;              // prologue scratch [4][128], aliased

    const int t  = threadIdx.x;
    const int tx = t & 15;
    const int ty = t >> 4;
    const int b   = blockIdx.x >> 3;
    const int hw0 = (blockIdx.x & 7) << 7;

    const float* zb = z + (size_t)b * DIM * HW + hw0;

    const uint32_t zs_base = (uint32_t)__cvta_generic_to_shared(zs);

    // ---- prologue: A[r] via NEON-4 strided reduce + ShuffleAndAdd order ----
#pragma unroll
    for (int s = 0; s < 2; ++s) {
        const int rj = t + 256 * s;
        const int r  = rj & 127;
        const int j  = rj >> 7;
        float acc = 0.f;
#pragma unroll 8
        for (int i = 0; i < DIM / 4; ++i) {
            float v = __ldg(zb + (size_t)(4 * i + j) * HW + r);
            acc = __fadd_rn(acc, __fmul_rn(v, v));
        }
        part4[j * 128 + r] = acc;
    }
    __syncthreads();
    if (t < 128) {
        float u0 = __fadd_rn(part4[0 * 128 + t], part4[2 * 128 + t]);
        float u1 = __fadd_rn(part4[1 * 128 + t], part4[3 * 128 + t]);
        As[t] = __fadd_rn(u0, u1);
    }
    __syncthreads();

    // init running argmin slots (each (row, tx) owned by exactly one thread)
#pragma unroll
    for (int i = 0; i < 8; ++i) {
        redv[(ty * 8 + i) * 16 + tx] = 3.402823466e38f;
        redi[(ty * 8 + i) * 16 + tx] = 0;
    }

    // per-thread load descriptors
    const int zq_c[4] = { (t + 0) >> 5, (t + 256) >> 5, (t + 512) >> 5, (t + 768) >> 5 };
    const int zq_g = t & 31;                         // 16B group within 128-float row
    const int wn  = t >> 1;                          // code row 0..127
    const int wco = (t & 1) * 16;                    // c offset within chunk (0 or 16)

    for (int nt = 0; nt < 8; ++nt) {
        const int n0 = nt << 7;

        float2 acc[8][4];
#pragma unroll
        for (int i = 0; i < 8; ++i)
#pragma unroll
            for (int j = 0; j < 4; ++j) acc[i][j] = make_float2(0.f, 0.f);

        // ---- prefetch chunk 0 ----
        float4 W[4];
        {
            const float* wsrc = cb + (size_t)(n0 + wn) * DIM + wco;
#pragma unroll
            for (int m = 0; m < 4; ++m) W[m] = __ldg((const float4*)wsrc + m);
#pragma unroll
            for (int q = 0; q < 4; ++q)
                cp_async16(zs_base + (uint32_t)((zq_c[q] * 128 + zq_g * 4) * 4),
                           zb + (size_t)zq_c[q] * HW + zq_g * 4);
            CP_COMMIT();
        }

        for (int kt = 0; kt < NCHUNK; ++kt) {
            const int p = kt & 1;
            float* wp = ws + p * 4096;
            const float* zp = zs + p * 4096;

            __syncthreads();   // all warps done computing chunk kt-1 (frees ws[p] from kt-2)

            // store W(kt) into ws[p] (transpose)
#pragma unroll
            for (int m = 0; m < 4; ++m) {
                const int cc = wco + m * 4;
                wp[(cc + 0) * 128 + wn] = W[m].x;
                wp[(cc + 1) * 128 + wn] = W[m].y;
                wp[(cc + 2) * 128 + wn] = W[m].z;
                wp[(cc + 3) * 128 + wn] = W[m].w;
            }
            // prefetch W(kt+1) into regs
            if (kt + 1 < NCHUNK) {
                const float* wsrc = cb + (size_t)(n0 + wn) * DIM + (kt + 1) * CHUNK + wco;
#pragma unroll
                for (int m = 0; m < 4; ++m) W[m] = __ldg((const float4*)wsrc + m);
            }

            CP_WAIT0();        // z(kt) landed
            __syncthreads();   // ws[p] stores + zs[p] visible to all

            // prefetch z(kt+1) into the other buffer
            if (kt + 1 < NCHUNK) {
                const int c1 = (kt + 1) * CHUNK;
                const uint32_t dst = zs_base + (uint32_t)((p ^ 1) * 4096 * 4);
#pragma unroll
                for (int q = 0; q < 4; ++q)
                    cp_async16(dst + (uint32_t)((zq_c[q] * 128 + zq_g * 4) * 4),
                               zb + (size_t)(c1 + zq_c[q]) * HW + zq_g * 4);
                CP_COMMIT();
            }

            // ---- compute: 32 ascending-c steps (chain order == reference) ----
#pragma unroll
            for (int kk = 0; kk < CHUNK; ++kk) {
                float a[8];
                *reinterpret_cast<float4*>(a) =
                    *reinterpret_cast<const float4*>(zp + kk * 128 + ty * 8);
                *reinterpret_cast<float4*>(a + 4) =
                    *reinterpret_cast<const float4*>(zp + kk * 128 + ty * 8 + 4);
                float2 bb[4];
                *reinterpret_cast<float4*>(&bb[0]) =
                    *reinterpret_cast<const float4*>(wp + kk * 128 + tx * 8);
                *reinterpret_cast<float4*>(&bb[2]) =
                    *reinterpret_cast<const float4*>(wp + kk * 128 + tx * 8 + 4);
#pragma unroll
                for (int i = 0; i < 8; ++i) {
                    float2 a2 = make_float2(a[i], a[i]);
#pragma unroll
                    for (int j = 0; j < 4; ++j) ffma2(acc[i][j], a2, bb[j]);
                }
            }
        }

        // epilogue: d = fl( fl(A - 2M) + C ); strict < keeps lowest index
#pragma unroll
        for (int i = 0; i < 8; ++i) {
            const int row = ty * 8 + i;
            float Ar = As[row];
            float bv = redv[row * 16 + tx];
            int   bi = redi[row * 16 + tx];
#pragma unroll
            for (int j = 0; j < 4; ++j) {
                float cn0 = g_codenorm[n0 + tx * 8 + 2 * j];
                float cn1 = g_codenorm[n0 + tx * 8 + 2 * j + 1];
                float d0 = __fadd_rn(__fadd_rn(Ar, __fmul_rn(-2.0f, acc[i][j].x)), cn0);
                float d1 = __fadd_rn(__fadd_rn(Ar, __fmul_rn(-2.0f, acc[i][j].y)), cn1);
                int   i0 = n0 + tx * 8 + 2 * j;
                if (d0 < bv) { bv = d0; bi = i0; }
                if (d1 < bv) { bv = d1; bi = i0 + 1; }
            }
            redv[row * 16 + tx] = bv;
            redi[row * 16 + tx] = bi;
        }
    }

    // final cross-tx reduction per row
    __syncthreads();
    if (t < 128) {
        float bv = redv[t * 16];
        int   bi = redi[t * 16];
#pragma unroll
        for (int x = 1; x < 16; ++x) {
            float v  = redv[t * 16 + x];
            int   ix = redi[t * 16 + x];
            if (v < bv || (v == bv && ix < bi)) { bv = v; bi = ix; }
        }
        int n = b * HW + hw0 + t;
        g_index[n] = bi;
        out[QUANT_ELEMS + n] = (float)bi;
    }
}

// ---------------------------------------------------------------------------
// Kernel 2: gather quantized = codebook[idx] (float4, codebook L2-resident)
// ---------------------------------------------------------------------------
__global__ void gather_kernel(const float* __restrict__ cb, float* __restrict__ out) {
    int i  = blockIdx.x * blockDim.x + threadIdx.x;
    int n  = i >> 7;
    int dd = i & 127;
    int idx = g_index[n];
    float4 v = __ldg(reinterpret_cast<const float4*>(cb) + (size_t)idx * 128 + dd);
    reinterpret_cast<float4*>(out)[i] = v;
}

// ---------------------------------------------------------------------------
extern "C" void kernel_launch(void* const* d_in, const int* in_sizes, int n_in,
                              void* d_out, int out_size) {
    const float* z  = (const float*)d_in[0];
    const float* cb = (const float*)d_in[1];
    float* out = (float*)d_out;

    const int smem_bytes = 20608 * 4;  // 82,432 B
    cudaFuncSetAttribute(vq_argmin_kernel,
                         cudaFuncAttributeMaxDynamicSharedMemorySize, smem_bytes);

    codenorm_kernel<<<K_CODES / 32, 128>>>(cb);
    vq_argmin_kernel<<<256, 256, smem_bytes>>>(z, cb, out);
    gather_kernel<<<QUANT_ELEMS / 4 / 256, 256>>>(cb, out);
}

// round 7
// speedup vs baseline: 1.0774x; 1.0014x over previous
#include <cuda_runtime.h>
#include <cstdint>

// Problem:
//   z:        [32, 512, 32, 32] f32  (B, C, H, W)
//   codebook: [1024, 512] f32        (K, D)
// Outputs (concatenated f32): quantized [16,777,216], then indices [32,768] as float.

#define N_ROWS   32768
#define K_CODES  1024
#define DIM      512
#define HW       1024
#define QUANT_ELEMS 16777216

#define CHUNK    32              // c per pipeline stage
#define NCHUNK   (DIM / CHUNK)   // 16

__device__ float g_codenorm[K_CODES];
__device__ int   g_index[N_ROWS];

// packed fp32x2 FMA (per-lane IEEE fma -> identical rounding to scalar chain)
__device__ __forceinline__ void ffma2(float2& d, float2 a, float2 b) {
    asm("fma.rn.f32x2 %0, %1, %2, %0;"
        : "+l"(reinterpret_cast<unsigned long long&>(d))
        : "l"(reinterpret_cast<unsigned long long&>(a)),
          "l"(reinterpret_cast<unsigned long long&>(b)));
}

__device__ __forceinline__ void cp_async16(uint32_t saddr, const void* g) {
    asm volatile("cp.async.ca.shared.global [%0], [%1], 16;\n"
                 :: "r"(saddr), "l"(g));
}
#define CP_COMMIT()  asm volatile("cp.async.commit_group;\n" ::: "memory")
#define CP_WAIT0()   asm volatile("cp.async.wait_group 0;\n" ::: "memory")

// ---------------------------------------------------------------------------
// Kernel 0: per-code norms, XLA CPU NEON-4 order:
//   t_j = sum_i fl(w[4i+j]^2);  C = fl( fl(t0+t2) + fl(t1+t3) )
// 128 threads = 32 codes x 4 lanes; shfl combine.
// ---------------------------------------------------------------------------
__global__ void codenorm_kernel(const float* __restrict__ cb) {
    const int t = threadIdx.x;
    const int j = t & 3;
    const int code = blockIdx.x * 32 + (t >> 2);
    const float* row = cb + (size_t)code * DIM;
    float acc = 0.f;
#pragma unroll 8
    for (int i = 0; i < DIM / 4; ++i) {
        float v = __ldg(row + 4 * i + j);
        acc = __fadd_rn(acc, __fmul_rn(v, v));
    }
    float u = __fadd_rn(acc, __shfl_down_sync(0xffffffffu, acc, 2)); // j0:t0+t2, j1:t1+t3
    float c = __fadd_rn(u,   __shfl_down_sync(0xffffffffu, u, 1));   // j0:(t0+t2)+(t1+t3)
    if (j == 0) g_codenorm[code] = c;
}

// ---------------------------------------------------------------------------
// Kernel 1: fused distance GEMM + argmin, double-buffered cp.async pipeline
// Block tile 128 rows x 128 codes; 256 threads, 8x8/thread, FFMA2.
// Dynamic smem layout (floats):
//   [0      .. 8192)  zs : 2 x 32 x 128   (z tile, [buf][c][row])
//   [8192   ..16384)  ws : 2 x 32 x 128   ([buf][c][code], transposed)
//   [16384  ..16512)  As : 128            (per-row ||z||^2, XLA order)
//   [16512  ..18560)  redv: 128 x 16      (running best value; aliases part4)
//   [18560  ..20608)  redi: 128 x 16      (running best index, int)
// ---------------------------------------------------------------------------
__global__ void __launch_bounds__(256, 2)
vq_argmin_kernel(const float* __restrict__ z, const float* __restrict__ cb,
                 float* __restrict__ out)
{
    extern __shared__ float sm[];
    float* zs   = sm;                 // [2][32][128]
    float* ws   = sm + 8192;          // [2][32][128]
    float* As   = sm + 16384;         // [128]
    float* redv = sm + 16512;         // [128][16]
    int*   redi = (int*)(sm + 18560); // [128][16]
    float* part4 = redv;              // prologue scratch [4][128], aliased

    const int t  = threadIdx.x;
    const int tx = t & 15;
    const int ty = t >> 4;
    const int b   = blockIdx.x >> 3;
    const int hw0 = (blockIdx.x & 7) << 7;

    const float* zb = z + (size_t)b * DIM * HW + hw0;

    const uint32_t zs_base = (uint32_t)__cvta_generic_to_shared(zs);

    // ---- prologue: A[r] via NEON-4 strided reduce + ShuffleAndAdd order ----
#pragma unroll
    for (int s = 0; s < 2; ++s) {
        const int rj = t + 256 * s;
        const int r  = rj & 127;
        const int j  = rj >> 7;
        float acc = 0.f;
#pragma unroll 8
        for (int i = 0; i < DIM / 4; ++i) {
            float v = __ldg(zb + (size_t)(4 * i + j) * HW + r);
            acc = __fadd_rn(acc, __fmul_rn(v, v));
        }
        part4[j * 128 + r] = acc;
    }
    __syncthreads();
    if (t < 128) {
        float u0 = __fadd_rn(part4[0 * 128 + t], part4[2 * 128 + t]);
        float u1 = __fadd_rn(part4[1 * 128 + t], part4[3 * 128 + t]);
        As[t] = __fadd_rn(u0, u1);
    }
    __syncthreads();

    // init running argmin slots (each (row, tx) owned by exactly one thread)
#pragma unroll
    for (int i = 0; i < 8; ++i) {
        redv[(ty * 8 + i) * 16 + tx] = 3.402823466e38f;
        redi[(ty * 8 + i) * 16 + tx] = 0;
    }

    // per-thread load descriptors
    const int zq_c[4] = { (t + 0) >> 5, (t + 256) >> 5, (t + 512) >> 5, (t + 768) >> 5 };
    const int zq_g = t & 31;                         // 16B group within 128-float row
    const int wn  = t >> 1;                          // code row 0..127
    const int wco = (t & 1) * 16;                    // c offset within chunk (0 or 16)

    for (int nt = 0; nt < 8; ++nt) {
        const int n0 = nt << 7;

        float2 acc[8][4];
#pragma unroll
        for (int i = 0; i < 8; ++i)
#pragma unroll
            for (int j = 0; j < 4; ++j) acc[i][j] = make_float2(0.f, 0.f);

        // ---- prefetch chunk 0 ----
        float4 W[4];
        {
            const float* wsrc = cb + (size_t)(n0 + wn) * DIM + wco;
#pragma unroll
            for (int m = 0; m < 4; ++m) W[m] = __ldg((const float4*)wsrc + m);
#pragma unroll
            for (int q = 0; q < 4; ++q)
                cp_async16(zs_base + (uint32_t)((zq_c[q] * 128 + zq_g * 4) * 4),
                           zb + (size_t)zq_c[q] * HW + zq_g * 4);
            CP_COMMIT();
        }

        for (int kt = 0; kt < NCHUNK; ++kt) {
            const int p = kt & 1;
            float* wp = ws + p * 4096;
            const float* zp = zs + p * 4096;

            __syncthreads();   // all warps done computing chunk kt-1 (frees ws[p] from kt-2)

            // store W(kt) into ws[p] (transpose)
#pragma unroll
            for (int m = 0; m < 4; ++m) {
                const int cc = wco + m * 4;
                wp[(cc + 0) * 128 + wn] = W[m].x;
                wp[(cc + 1) * 128 + wn] = W[m].y;
                wp[(cc + 2) * 128 + wn] = W[m].z;
                wp[(cc + 3) * 128 + wn] = W[m].w;
            }
            // prefetch W(kt+1) into regs
            if (kt + 1 < NCHUNK) {
                const float* wsrc = cb + (size_t)(n0 + wn) * DIM + (kt + 1) * CHUNK + wco;
#pragma unroll
                for (int m = 0; m < 4; ++m) W[m] = __ldg((const float4*)wsrc + m);
            }

            CP_WAIT0();        // z(kt) landed
            __syncthreads();   // ws[p] stores + zs[p] visible to all

            // prefetch z(kt+1) into the other buffer
            if (kt + 1 < NCHUNK) {
                const int c1 = (kt + 1) * CHUNK;
                const uint32_t dst = zs_base + (uint32_t)((p ^ 1) * 4096 * 4);
#pragma unroll
                for (int q = 0; q < 4; ++q)
                    cp_async16(dst + (uint32_t)((zq_c[q] * 128 + zq_g * 4) * 4),
                               zb + (size_t)(c1 + zq_c[q]) * HW + zq_g * 4);
                CP_COMMIT();
            }

            // ---- compute: 32 ascending-c steps (chain order == reference) ----
#pragma unroll
            for (int kk = 0; kk < CHUNK; ++kk) {
                float a[8];
                *reinterpret_cast<float4*>(a) =
                    *reinterpret_cast<const float4*>(zp + kk * 128 + ty * 8);
                *reinterpret_cast<float4*>(a + 4) =
                    *reinterpret_cast<const float4*>(zp + kk * 128 + ty * 8 + 4);
                float2 bb[4];
                *reinterpret_cast<float4*>(&bb[0]) =
                    *reinterpret_cast<const float4*>(wp + kk * 128 + tx * 8);
                *reinterpret_cast<float4*>(&bb[2]) =
                    *reinterpret_cast<const float4*>(wp + kk * 128 + tx * 8 + 4);
#pragma unroll
                for (int i = 0; i < 8; ++i) {
                    float2 a2 = make_float2(a[i], a[i]);
#pragma unroll
                    for (int j = 0; j < 4; ++j) ffma2(acc[i][j], a2, bb[j]);
                }
            }
        }

        // epilogue: d = fl( fl(A - 2M) + C ); strict < keeps lowest index
#pragma unroll
        for (int i = 0; i < 8; ++i) {
            const int row = ty * 8 + i;
            float Ar = As[row];
            float bv = redv[row * 16 + tx];
            int   bi = redi[row * 16 + tx];
#pragma unroll
            for (int j = 0; j < 4; ++j) {
                float cn0 = g_codenorm[n0 + tx * 8 + 2 * j];
                float cn1 = g_codenorm[n0 + tx * 8 + 2 * j + 1];
                float d0 = __fadd_rn(__fadd_rn(Ar, __fmul_rn(-2.0f, acc[i][j].x)), cn0);
                float d1 = __fadd_rn(__fadd_rn(Ar, __fmul_rn(-2.0f, acc[i][j].y)), cn1);
                int   i0 = n0 + tx * 8 + 2 * j;
                if (d0 < bv) { bv = d0; bi = i0; }
                if (d1 < bv) { bv = d1; bi = i0 + 1; }
            }
            redv[row * 16 + tx] = bv;
            redi[row * 16 + tx] = bi;
        }
    }

    // final cross-tx reduction per row
    __syncthreads();
    if (t < 128) {
        float bv = redv[t * 16];
        int   bi = redi[t * 16];
#pragma unroll
        for (int x = 1; x < 16; ++x) {
            float v  = redv[t * 16 + x];
            int   ix = redi[t * 16 + x];
            if (v < bv || (v == bv && ix < bi)) { bv = v; bi = ix; }
        }
        int n = b * HW + hw0 + t;
        g_index[n] = bi;
        out[QUANT_ELEMS + n] = (float)bi;
    }
}

// ---------------------------------------------------------------------------
// Kernel 2: gather quantized = codebook[idx] (float4, codebook L2-resident)
// ---------------------------------------------------------------------------
__global__ void gather_kernel(const float* __restrict__ cb, float* __restrict__ out) {
    int i  = blockIdx.x * blockDim.x + threadIdx.x;
    int n  = i >> 7;
    int dd = i & 127;
    int idx = g_index[n];
    float4 v = __ldg(reinterpret_cast<const float4*>(cb) + (size_t)idx * 128 + dd);
    reinterpret_cast<float4*>(out)[i] = v;
}

// ---------------------------------------------------------------------------
extern "C" void kernel_launch(void* const* d_in, const int* in_sizes, int n_in,
                              void* d_out, int out_size) {
    const float* z  = (const float*)d_in[0];
    const float* cb = (const float*)d_in[1];
    float* out = (float*)d_out;

    const int smem_bytes = 20608 * 4;  // 82,432 B
    cudaFuncSetAttribute(vq_argmin_kernel,
                         cudaFuncAttributeMaxDynamicSharedMemorySize, smem_bytes);

    codenorm_kernel<<<K_CODES / 32, 128>>>(cb);
    vq_argmin_kernel<<<256, 256, smem_bytes>>>(z, cb, out);
    gather_kernel<<<QUANT_ELEMS / 4 / 256, 256>>>(cb, out);
}